// round 14
// baseline (speedup 1.0000x reference)
#include <cuda_runtime.h>

#define NQ      12
#define NT      256
#define NWARP   8
#define LAYERS  4
#define NENC    4
#define MAXB    1024

typedef unsigned long long u64;

// ---------------- static device scratch (no allocations) ----------------
__device__ float g_branch[NENC * MAXB * NQ];
// real-Y gate coefficients (built by prep, mirrored into __constant__):
// per (l,q) 4 u64. q<11: [ (c,c), (s,s), 0, 0 ].
// q=11 (amp bit 0): [ dA=(c,c), oA=(-s,s), dB=(s,-s), oB=(c,c) ].
__device__ u64   g_vry[LAYERS * NQ * 4];
__constant__ u64 c_vry[LAYERS * NQ * 4];
// ZYZ diagonal angles per (l,q)
__device__ float g_alpha[LAYERS * NQ];
__device__ float g_gamma[LAYERS * NQ];
// boundary diagonals (theta-only, shared by all CTAs), LAYOUT-B indexing:
// slot = (j<<8)|(w<<5)|lane  ->  amp pair xp = (j<<8)|(lane<<3)|w
__device__ ulonglong2 g_diag[3 * 2048];
// encoding columns (gamma_1 folded): (c0.x, c0.y, c1.x, c1.y)
__device__ float4 g_em[NENC * MAXB * NQ];

// ---------------- scalar complex helpers (prep + encoding) ----------------
__device__ __forceinline__ float2 cmul(float2 a, float2 b) {
    return make_float2(fmaf(a.x, b.x, -a.y * b.y), fmaf(a.x, b.y, a.y * b.x));
}
__device__ __forceinline__ float2 cadd(float2 a, float2 b) {
    return make_float2(a.x + b.x, a.y + b.y);
}
struct M2 { float2 m00, m01, m10, m11; };
__device__ __forceinline__ M2 mmul(const M2& A, const M2& B) {
    M2 C;
    C.m00 = cadd(cmul(A.m00, B.m00), cmul(A.m01, B.m10));
    C.m01 = cadd(cmul(A.m00, B.m01), cmul(A.m01, B.m11));
    C.m10 = cadd(cmul(A.m10, B.m00), cmul(A.m11, B.m10));
    C.m11 = cadd(cmul(A.m10, B.m01), cmul(A.m11, B.m11));
    return C;
}
__device__ __forceinline__ M2 rx_m(float t) {
    float s, c; sincosf(0.5f * t, &s, &c);
    M2 M; M.m00 = {c, 0.f}; M.m01 = {0.f, -s}; M.m10 = {0.f, -s}; M.m11 = {c, 0.f};
    return M;
}
__device__ __forceinline__ M2 ry_m(float t) {
    float s, c; sincosf(0.5f * t, &s, &c);
    M2 M; M.m00 = {c, 0.f}; M.m01 = {-s, 0.f}; M.m10 = {s, 0.f}; M.m11 = {c, 0.f};
    return M;
}
__device__ __forceinline__ M2 rz_m(float t) {
    float s, c; sincosf(0.5f * t, &s, &c);
    M2 M; M.m00 = {c, -s}; M.m01 = {0.f, 0.f}; M.m10 = {0.f, 0.f}; M.m11 = {c, s};
    return M;
}

// ---------------- packed f32x2 primitives ----------------
__device__ __forceinline__ u64 pk2(float x, float y) {
    u64 r; asm("mov.b64 %0, {%1, %2};" : "=l"(r) : "f"(x), "f"(y)); return r;
}
__device__ __forceinline__ void upk2(u64 v, float& x, float& y) {
    asm("mov.b64 {%0, %1}, %2;" : "=f"(x), "=f"(y) : "l"(v));
}
__device__ __forceinline__ u64 pswap(u64 v) {
    float x, y; upk2(v, x, y); return pk2(y, x);
}
__device__ __forceinline__ u64 pmul(u64 a, u64 b) {
    u64 r; asm("mul.rn.f32x2 %0, %1, %2;" : "=l"(r) : "l"(a), "l"(b)); return r;
}
__device__ __forceinline__ u64 pfma(u64 a, u64 b, u64 c) {
    u64 r; asm("fma.rn.f32x2 %0, %1, %2, %3;" : "=l"(r) : "l"(a), "l"(b), "l"(c)); return r;
}
__device__ __forceinline__ u64 shfl64(u64 v, int m) {
    float x, y; upk2(v, x, y);
    x = __shfl_xor_sync(0xffffffffu, x, m);
    y = __shfl_xor_sync(0xffffffffu, y, m);
    return pk2(x, y);
}

#define SIGNMASK 0x8000000080000000ULL

// ---------------- prep kernels ----------------
__global__ void prep_var_kernel(const float* __restrict__ theta) {
    int idx = blockIdx.x * blockDim.x + threadIdx.x;        // l*NQ + q
    if (idx >= LAYERS * NQ) return;
    int q = idx % NQ;
    const float* th = theta + idx * 3;
    M2 M = mmul(rz_m(th[2]), mmul(ry_m(th[1]), rx_m(th[0])));
    float c = sqrtf(fmaf(M.m00.x, M.m00.x, M.m00.y * M.m00.y));
    float s = sqrtf(fmaf(M.m10.x, M.m10.x, M.m10.y * M.m10.y));
    float p00 = atan2f(M.m00.y, M.m00.x);
    float p10 = atan2f(M.m10.y, M.m10.x);
    g_alpha[idx] = p10 - p00;
    g_gamma[idx] = -p10 - p00;
    u64* dst = g_vry + idx * 4;
    if (q < 11) {
        dst[0] = pk2(c, c); dst[1] = pk2(s, s);
        dst[2] = 0; dst[3] = 0;
    } else {
        dst[0] = pk2(c, c);   dst[1] = pk2(-s, s);    // set A (even j)
        dst[2] = pk2(s, -s);  dst[3] = pk2(c, c);     // set B (odd j, row-swapped)
    }
}

// boundary diagonal l, LAYOUT-B slot indexing:
//   slot idx = (j<<8)|(w<<5)|lane; amp pair xp = (j<<8)|(lane<<3)|w
//   delta_l(x) = d_alpha[l](Ce x) * d_gamma[l+1](Co x)
__global__ void prep_diag_kernel() {
    int idx = blockIdx.x * blockDim.x + threadIdx.x;
    if (idx >= 3 * 2048) return;
    int l    = idx >> 11;
    int slot = idx & 2047;
    int j    = (slot >> 8) & 7;
    int w    = (slot >> 5) & 7;
    int lane = slot & 31;
    int xp   = (j << 8) | (lane << 3) | w;      // layout B
    const float* al = g_alpha + l * NQ;
    const float* gm = g_gamma + (l + 1) * NQ;
    float rr[2], ii[2];
    #pragma unroll
    for (int h = 0; h < 2; h++) {
        int x  = (xp << 1) | h;
        int ye = x ^ ((x >> 1) & 0x555);
        int yo = x ^ ((x >> 1) & 0x2AA);
        float ang = 0.f;
        for (int q = 0; q < NQ; q++) {
            int p = 11 - q;
            ang += ((ye >> p) & 1) ? 0.5f * al[q] : -0.5f * al[q];
            ang += ((yo >> p) & 1) ? 0.5f * gm[q] : -0.5f * gm[q];
        }
        float sn, cs; sincosf(ang, &sn, &cs);
        rr[h] = cs; ii[h] = sn;
    }
    g_diag[idx] = make_ulonglong2(pk2(rr[0], rr[1]), pk2(ii[0], ii[1]));
}

__global__ void prep_enc_kernel(const float* __restrict__ features, int B) {
    int idx = blockIdx.x * blockDim.x + threadIdx.x;        // e*B*NQ + b*NQ + q
    if (idx >= NENC * B * NQ) return;
    int q = idx % NQ;
    int b = (idx / NQ) % B;
    int e = idx / (B * NQ);
    float f = features[b * NQ + q];
    M2 R = (e & 1) ? ry_m(f) : rx_m(f);
    if (e >= 2) {
        const float r = 0.7071067811865476f;
        M2 H; H.m00 = {r, 0.f}; H.m01 = {r, 0.f}; H.m10 = {r, 0.f}; H.m11 = {-r, 0.f};
        R = mmul(R, H);
    }
    float g = g_gamma[q];          // fold layer-1 gamma diagonal
    float sg, cg; sincosf(0.5f * g, &sg, &cg);
    float2 c0 = cmul(make_float2(R.m00.x, R.m00.y), make_float2(cg, -sg));
    float2 c1 = cmul(make_float2(R.m10.x, R.m10.y), make_float2(cg, sg));
    g_em[idx] = make_float4(c0.x, c0.y, c1.x, c1.y);
}

// ---------------- real-rotation gate primitives ----------------
// Layout A: amp = (w<<9)|(lane<<4)|(j<<1)|h.
// Layout B: amp = (j<<9)|(lane<<4)|(w<<1)|h  (after transpose3).
// sr[j]/si[j] hold (h=0, h=1) packed per f32x2.

__device__ __forceinline__ void ldRG(const u64* __restrict__ p, u64& c, u64& s) {
    c = p[0]; s = p[1];
}

template<int JB, int PREJ, int POSTJ>
__device__ __forceinline__ void gate_jr(u64 sr[8], u64 si[8],
                                        u64 P00, u64 P01, u64 P10, u64 P11) {
    #pragma unroll
    for (int j = 0; j < 8; j++) {
        if (!(j & JB)) {
            const int j1 = j | JB;
            const bool pre  = (PREJ != 0) && ((j & PREJ) != 0);
            const bool post = (POSTJ != 0) && ((j & POSTJ) != 0);
            const int ja = pre ? j1 : j, jb = pre ? j : j1;
            u64 Ar = sr[ja], Ai = si[ja], Br = sr[jb], Bi = si[jb];
            u64 o0r = pfma(P01, Br, pmul(P00, Ar));
            u64 o0i = pfma(P01, Bi, pmul(P00, Ai));
            u64 o1r = pfma(P11, Br, pmul(P10, Ar));
            u64 o1i = pfma(P11, Bi, pmul(P10, Ai));
            sr[post ? j1 : j] = o0r; si[post ? j1 : j] = o0i;
            sr[post ? j : j1] = o1r; si[post ? j : j1] = o1i;
        }
    }
}

__device__ __forceinline__ void gate_laner(u64 sr[8], u64 si[8], u64 c, u64 s,
                                           int mask, int lane, bool cswap, bool rxor) {
    u64 ns = s ^ SIGNMASK;
    const bool hi   = (lane & mask) != 0;
    const bool row  = hi ^ rxor;
    const bool scol = hi ^ cswap;
    u64 sgn = row ? s : ns;
    u64 P = (row == scol) ? c : sgn;
    u64 Q = (row == scol) ? sgn : c;
    #pragma unroll
    for (int j = 0; j < 8; j++) {
        u64 orr = shfl64(sr[j], mask);
        u64 oii = shfl64(si[j], mask);
        sr[j] = pfma(Q, orr, pmul(P, sr[j]));
        si[j] = pfma(Q, oii, pmul(P, si[j]));
    }
}

// b8 lane gate in LAYOUT B: mask 16, post CNOT row-swap controlled by b9 = j bit 0.
__device__ __forceinline__ void gate_laner_b8(u64 sr[8], u64 si[8], u64 c, u64 s, int lane) {
    u64 ns = s ^ SIGNMASK;
    const bool hi = (lane & 16) != 0;
    u64 Qe = hi ? s : ns;      // even j: P=c, Q=M[hi][hi^1]
    u64 Po = hi ? ns : s;      // odd j:  P=M[hi^1][hi], Q=c
    #pragma unroll
    for (int j = 0; j < 8; j++) {
        u64 orr = shfl64(sr[j], 16);
        u64 oii = shfl64(si[j], 16);
        if (j & 1) {
            sr[j] = pfma(c, orr, pmul(Po, sr[j]));
            si[j] = pfma(c, oii, pmul(Po, si[j]));
        } else {
            sr[j] = pfma(Qe, orr, pmul(c, sr[j]));
            si[j] = pfma(Qe, oii, pmul(c, si[j]));
        }
    }
}

// wire-11 gate on amp bit 0 (within-u64); post CNOT(ctrl=b1) fused via set B
__device__ __forceinline__ void gate_hr(u64 sr[8], u64 si[8], const u64* __restrict__ p) {
    u64 dA = p[0], oA = p[1], dB = p[2], oB = p[3];
    #pragma unroll
    for (int j = 0; j < 8; j++) {
        u64 d = (j & 1) ? dB : dA;
        u64 o = (j & 1) ? oB : oA;
        sr[j] = pfma(o, pswap(sr[j]), pmul(d, sr[j]));
        si[j] = pfma(o, pswap(si[j]), pmul(d, si[j]));
    }
}

// boundary diagonal: per-amp complex multiply (state in LAYOUT B)
__device__ __forceinline__ void apply_diag(u64 sr[8], u64 si[8],
                                           const ulonglong2* __restrict__ tab, int tid) {
    #pragma unroll
    for (int j = 0; j < 8; j++) {
        ulonglong2 v = tab[(j << 8) | tid];
        u64 dr = v.x, di = v.y, dni = di ^ SIGNMASK;
        u64 nr = pfma(dni, si[j], pmul(dr, sr[j]));
        u64 ni = pfma(dr,  si[j], pmul(di, sr[j]));
        sr[j] = nr; si[j] = ni;
    }
}

// ---------------- layout transpose: amp bits 1-3 <-> 9-11 ----------------
template<bool HIGHSTORE>
__device__ __forceinline__ void transpose3(u64 sr[8], u64 si[8],
                                           ulonglong2* __restrict__ buf,
                                           int lane, int w) {
    #pragma unroll
    for (int j = 0; j < 8; j++) {
        int u = HIGHSTORE ? ((j << 8) | (lane << 3) | w)
                          : ((w << 8) | (lane << 3) | j);
        buf[u ^ (lane & 7)] = make_ulonglong2(sr[j], si[j]);
    }
    __syncthreads();
    #pragma unroll
    for (int j = 0; j < 8; j++) {
        int u = HIGHSTORE ? ((w << 8) | (lane << 3) | j)
                          : ((j << 8) | (lane << 3) | w);
        ulonglong2 v = buf[u ^ (lane & 7)];
        sr[j] = v.x; si[j] = v.y;
    }
}

// Sweep: [A-phase] T(A->B) [B-phase (+diag)] T(B->A unless LAST).
// A-phase (layout A): b1,b3 (reg, pre), b7,b5 (lane, pre), b2,b0 (reg, post),
// b6,b4 (lane, post). B-phase (layout B): b11, b9(pre), b10(post) reg;
// b8 lane with per-j post row swap (ctrl b9 = j bit0). All CNOT-absorption
// precedence edges verified: pre gates before their ctrl-bit gates, post
// gates after their ctrl-bit gates, absorbed CNOTs disjoint from interposers.
template<bool PRE, bool LAST>
__device__ __forceinline__ void vsweep2(const u64* __restrict__ m,
                                        const ulonglong2* __restrict__ dtab,
                                        u64 sr[8], u64 si[8],
                                        ulonglong2* bufAB, ulonglong2* bufBA,
                                        int lane, int w, int tid) {
    u64 c, s, ns;
    // ---- phase A ----
    ldRG(m + 10*4, c, s); ns = s ^ SIGNMASK;                        // b1 (wire 10), pre c=b2
    if (PRE) gate_jr<1, 2, 0>(sr, si, c, ns, s, c);
    else     gate_jr<1, 0, 0>(sr, si, c, ns, s, c);
    ldRG(m + 8*4, c, s); ns = s ^ SIGNMASK;                         // b3 (wire 8), pre c=b4 (lane bit0)
    {
        bool cs3 = PRE && (lane & 1);
        u64 q00 = cs3 ? ns : c, q01 = cs3 ? c : ns;
        u64 q10 = cs3 ? c : s,  q11v = cs3 ? s : c;
        gate_jr<4, 0, 0>(sr, si, q00, q01, q10, q11v);
    }
    ldRG(m + 4*4, c, s);                                            // b7 (wire 4), pre c=b8
    gate_laner(sr, si, c, s, 8, lane, PRE && (lane & 16), false);
    ldRG(m + 6*4, c, s);                                            // b5 (wire 6), pre c=b6
    gate_laner(sr, si, c, s, 2, lane, PRE && (lane & 4), false);
    ldRG(m + 9*4, c, s); ns = s ^ SIGNMASK;                         // b2 (wire 9), post c=b3
    gate_jr<2, 0, 4>(sr, si, c, ns, s, c);
    gate_hr(sr, si, m + 11*4);                                      // b0 (wire 11), post c=b1
    ldRG(m + 5*4, c, s);                                            // b6 (wire 5), post c=b7
    gate_laner(sr, si, c, s, 4, lane, false, (lane & 8) != 0);
    ldRG(m + 7*4, c, s);                                            // b4 (wire 7), post c=b5
    gate_laner(sr, si, c, s, 1, lane, false, (lane & 2) != 0);
    // ---- T(A->B) ----
    transpose3<false>(sr, si, bufAB, lane, w);
    // ---- phase B ----
    ldRG(m + 0*4, c, s); ns = s ^ SIGNMASK;                         // b11 (wire 0)
    gate_jr<4, 0, 0>(sr, si, c, ns, s, c);
    ldRG(m + 2*4, c, s); ns = s ^ SIGNMASK;                         // b9 (wire 2), pre c=b10 (j bit1)
    if (PRE) gate_jr<1, 2, 0>(sr, si, c, ns, s, c);
    else     gate_jr<1, 0, 0>(sr, si, c, ns, s, c);
    ldRG(m + 1*4, c, s); ns = s ^ SIGNMASK;                         // b10 (wire 1), post c=b11 (j bit2)
    gate_jr<2, 0, 4>(sr, si, c, ns, s, c);
    ldRG(m + 3*4, c, s);                                            // b8 (wire 3), post c=b9 (j bit0)
    gate_laner_b8(sr, si, c, s, lane);
    if (!LAST) {
        apply_diag(sr, si, dtab, tid);
        transpose3<true>(sr, si, bufBA, lane, w);
    }
}

// ---------------- main kernel ----------------
__global__ __launch_bounds__(NT, 2)
void vqc_reg_kernel(int B)
{
    extern __shared__ ulonglong2 dynbuf[];   // [0..2047] bufAB, [2048..4095] bufBA
    __shared__ float red[NWARP * NQ];
    ulonglong2* bufAB = dynbuf;
    ulonglong2* bufBA = dynbuf + 2048;

    const int b    = blockIdx.x;
    const int e    = blockIdx.y;
    const int tid  = threadIdx.x;
    const int lane = tid & 31;
    const int w    = tid >> 5;

    // ---- encoding: direct product-state construction (layout A) ----
    const float4* col = g_em + (e * B + b) * NQ;
    float2 ph;
    {
        float4 c0 = col[0];
        ph = ((tid >> 7) & 1) ? make_float2(c0.z, c0.w) : make_float2(c0.x, c0.y);
        #pragma unroll
        for (int q = 1; q < 8; q++) {
            float4 cq = col[q];
            float2 v = ((tid >> (7 - q)) & 1) ? make_float2(cq.z, cq.w)
                                              : make_float2(cq.x, cq.y);
            ph = cmul(ph, v);
        }
    }
    u64 sr[8], si[8];
    {
        float4 c8 = col[8], c9 = col[9], c10 = col[10], c11 = col[11];
        float2 t2[2], t4[4], t8[8];
        t2[0] = cmul(ph, make_float2(c8.x, c8.y));
        t2[1] = cmul(ph, make_float2(c8.z, c8.w));
        #pragma unroll
        for (int i = 0; i < 2; i++) {
            t4[i*2+0] = cmul(t2[i], make_float2(c9.x, c9.y));
            t4[i*2+1] = cmul(t2[i], make_float2(c9.z, c9.w));
        }
        #pragma unroll
        for (int i = 0; i < 4; i++) {
            t8[i*2+0] = cmul(t4[i], make_float2(c10.x, c10.y));
            t8[i*2+1] = cmul(t4[i], make_float2(c10.z, c10.w));
        }
        #pragma unroll
        for (int j = 0; j < 8; j++) {
            float2 a  = cmul(t8[j], make_float2(c11.x, c11.y));   // h = 0
            float2 bm = cmul(t8[j], make_float2(c11.z, c11.w));   // h = 1
            sr[j] = pk2(a.x, bm.x);
            si[j] = pk2(a.y, bm.y);
        }
    }

    // ---- variational layers ----
    vsweep2<false, false>(c_vry + 0*48, g_diag + 0*2048, sr, si, bufAB, bufBA, lane, w, tid);
    vsweep2<true,  false>(c_vry + 1*48, g_diag + 1*2048, sr, si, bufAB, bufBA, lane, w, tid);
    vsweep2<true,  false>(c_vry + 2*48, g_diag + 2*2048, sr, si, bufAB, bufBA, lane, w, tid);
    vsweep2<true,  true >(c_vry + 3*48, (const ulonglong2*)0, sr, si, bufAB, bufBA, lane, w, tid);
    // state ends in LAYOUT B: amp = (j<<9)|(lane<<4)|(w<<1)|h
    // alpha_4 drops at measurement; layer-4 odd ladder -> epilogue sign
    // permutation: b9^=b10, b7^=b8, b5^=b6, b3^=b4, b1^=b2

    // ---- <Z_q>, layout-B bit mapping ----
    // k = 2j+h: k bit0 = b0, k bits 1-3 = b9,b10,b11. tid bits 0-4 = b4..b8,
    // tid bits 5-7 = b1,b2,b3.
    float t[16], tot = 0.f;
    #pragma unroll
    for (int j = 0; j < 8; j++) {
        u64 p2 = pfma(si[j], si[j], pmul(sr[j], sr[j]));
        float p0, p1; upk2(p2, p0, p1);
        t[2*j] = p0; t[2*j+1] = p1;
        tot += p0 + p1;
    }
    float aq0 = 0.f, aq1 = 0.f, aq2 = 0.f, aq11 = 0.f;
    #pragma unroll
    for (int k = 0; k < 16; k++) {
        aq0  += (k & 8) ? -t[k] : t[k];                      // b11   (k bit 3)
        aq1  += (k & 4) ? -t[k] : t[k];                      // b10   (k bit 2)
        aq2  += (((k >> 1) ^ (k >> 2)) & 1) ? -t[k] : t[k];  // b9^b10
        aq11 += (k & 1) ? -t[k] : t[k];                      // b0    (k bit 0)
    }
    float ez[NQ];
    ez[0]  = aq0;
    ez[1]  = aq1;
    ez[2]  = aq2;
    ez[3]  = ((tid >> 4) & 1)                   ? -tot : tot;  // b8
    ez[4]  = (((tid >> 3) ^ (tid >> 4)) & 1)    ? -tot : tot;  // b7^b8
    ez[5]  = ((tid >> 2) & 1)                   ? -tot : tot;  // b6
    ez[6]  = (((tid >> 1) ^ (tid >> 2)) & 1)    ? -tot : tot;  // b5^b6
    ez[7]  = (tid & 1)                          ? -tot : tot;  // b4
    ez[8]  = (((tid >> 7) ^ tid) & 1)           ? -tot : tot;  // b3^b4
    ez[9]  = ((tid >> 6) & 1)                   ? -tot : tot;  // b2
    ez[10] = (((tid >> 5) ^ (tid >> 6)) & 1)    ? -tot : tot;  // b1^b2
    ez[11] = aq11;

    #pragma unroll
    for (int q = 0; q < NQ; q++)
        #pragma unroll
        for (int o = 16; o > 0; o >>= 1)
            ez[q] += __shfl_xor_sync(0xffffffffu, ez[q], o);

    if (lane == 0) {
        #pragma unroll
        for (int q = 0; q < NQ; q++) red[w * NQ + q] = ez[q];
    }
    __syncthreads();
    if (tid < NQ) {
        float acc = 0.f;
        #pragma unroll
        for (int j = 0; j < NWARP; j++) acc += red[j * NQ + tid];
        g_branch[(e * B + b) * NQ + tid] = acc;
    }
}

// ---------------- softmax(alpha)-weighted branch mix ----------------
__global__ void reduce_kernel(const float* __restrict__ alpha,
                              float* __restrict__ out, int B)
{
    int idx = blockIdx.x * blockDim.x + threadIdx.x;
    if (idx >= B * NQ) return;
    float a0 = alpha[0], a1 = alpha[1], a2 = alpha[2], a3 = alpha[3];
    float m  = fmaxf(fmaxf(a0, a1), fmaxf(a2, a3));
    float w0 = expf(a0 - m), w1 = expf(a1 - m), w2 = expf(a2 - m), w3 = expf(a3 - m);
    float inv = 1.f / (w0 + w1 + w2 + w3);
    int stride = B * NQ;
    float y = w0 * g_branch[idx]
            + w1 * g_branch[stride + idx]
            + w2 * g_branch[2 * stride + idx]
            + w3 * g_branch[3 * stride + idx];
    out[idx] = y * inv;
}

extern "C" void kernel_launch(void* const* d_in, const int* in_sizes, int n_in,
                              void* d_out, int out_size)
{
    const float* features = (const float*)d_in[0];   // (B, 12)
    const float* theta    = (const float*)d_in[1];   // (4, 12, 3)
    const float* alpha    = (const float*)d_in[2];   // (4,)
    float* out = (float*)d_out;                      // (B, 12)

    int B = in_sizes[0] / NQ;
    if (B > MAXB) B = MAXB;

    const int SMEM_DYN = 4096 * (int)sizeof(ulonglong2);   // 64 KB double buffer
    cudaFuncSetAttribute(vqc_reg_kernel,
                         cudaFuncAttributeMaxDynamicSharedMemorySize, SMEM_DYN);

    prep_var_kernel<<<1, 64>>>(theta);            // writes g_vry, g_alpha, g_gamma

    // mirror gate coefficients into __constant__ (D2D async copy, graph-legal)
    void* vry_dev = 0;
    cudaGetSymbolAddress(&vry_dev, g_vry);
    cudaMemcpyToSymbolAsync(c_vry, vry_dev, sizeof(u64) * LAYERS * NQ * 4, 0,
                            cudaMemcpyDeviceToDevice, 0);

    prep_diag_kernel<<<24, 256>>>();              // reads g_alpha/g_gamma
    int nenc = NENC * B * NQ;
    prep_enc_kernel<<<(nenc + 255) / 256, 256>>>(features, B);  // reads g_gamma

    dim3 grid(B, NENC);
    vqc_reg_kernel<<<grid, NT, SMEM_DYN>>>(B);

    int n = B * NQ;
    reduce_kernel<<<(n + 255) / 256, 256>>>(alpha, out, B);
}

// round 15
// speedup vs baseline: 1.0106x; 1.0106x over previous
#include <cuda_runtime.h>

#define NQ      12
#define NT      256
#define NWARP   8
#define LAYERS  4
#define NENC    4
#define MAXB    1024

typedef unsigned long long u64;

// ---------------- static device scratch (no allocations) ----------------
__device__ float g_branch[NENC * MAXB * NQ];
// t-form gate coefficients: 1 u64 per (l,q): (t,t); q=11 stores (-t,+t).
__device__ u64   g_vry[LAYERS * NQ];
__constant__ u64 c_vry[LAYERS * NQ];
__device__ float g_cs[LAYERS * NQ];       // per-gate c (for the global scale)
__device__ float g_scale;                 // prod over all 48 gates of c^2
// ZYZ diagonal angles per (l,q)
__device__ float g_alpha[LAYERS * NQ];
__device__ float g_gamma[LAYERS * NQ];
// boundary diagonals (theta-only, shared by all CTAs), LAYOUT-B indexing:
// slot = (j<<8)|(w<<5)|lane  ->  amp pair xp = (j<<8)|(lane<<3)|w
__device__ ulonglong2 g_diag[3 * 2048];
// encoding columns (gamma_1 folded): (c0.x, c0.y, c1.x, c1.y)
__device__ float4 g_em[NENC * MAXB * NQ];

// ---------------- scalar complex helpers (prep + encoding) ----------------
__device__ __forceinline__ float2 cmul(float2 a, float2 b) {
    return make_float2(fmaf(a.x, b.x, -a.y * b.y), fmaf(a.x, b.y, a.y * b.x));
}
__device__ __forceinline__ float2 cadd(float2 a, float2 b) {
    return make_float2(a.x + b.x, a.y + b.y);
}
struct M2 { float2 m00, m01, m10, m11; };
__device__ __forceinline__ M2 mmul(const M2& A, const M2& B) {
    M2 C;
    C.m00 = cadd(cmul(A.m00, B.m00), cmul(A.m01, B.m10));
    C.m01 = cadd(cmul(A.m00, B.m01), cmul(A.m01, B.m11));
    C.m10 = cadd(cmul(A.m10, B.m00), cmul(A.m11, B.m10));
    C.m11 = cadd(cmul(A.m10, B.m01), cmul(A.m11, B.m11));
    return C;
}
__device__ __forceinline__ M2 rx_m(float t) {
    float s, c; sincosf(0.5f * t, &s, &c);
    M2 M; M.m00 = {c, 0.f}; M.m01 = {0.f, -s}; M.m10 = {0.f, -s}; M.m11 = {c, 0.f};
    return M;
}
__device__ __forceinline__ M2 ry_m(float t) {
    float s, c; sincosf(0.5f * t, &s, &c);
    M2 M; M.m00 = {c, 0.f}; M.m01 = {-s, 0.f}; M.m10 = {s, 0.f}; M.m11 = {c, 0.f};
    return M;
}
__device__ __forceinline__ M2 rz_m(float t) {
    float s, c; sincosf(0.5f * t, &s, &c);
    M2 M; M.m00 = {c, -s}; M.m01 = {0.f, 0.f}; M.m10 = {0.f, 0.f}; M.m11 = {c, s};
    return M;
}

// ---------------- packed f32x2 primitives ----------------
__device__ __forceinline__ u64 pk2(float x, float y) {
    u64 r; asm("mov.b64 %0, {%1, %2};" : "=l"(r) : "f"(x), "f"(y)); return r;
}
__device__ __forceinline__ void upk2(u64 v, float& x, float& y) {
    asm("mov.b64 {%0, %1}, %2;" : "=f"(x), "=f"(y) : "l"(v));
}
__device__ __forceinline__ u64 pswap(u64 v) {
    float x, y; upk2(v, x, y); return pk2(y, x);
}
__device__ __forceinline__ u64 pmul(u64 a, u64 b) {
    u64 r; asm("mul.rn.f32x2 %0, %1, %2;" : "=l"(r) : "l"(a), "l"(b)); return r;
}
__device__ __forceinline__ u64 pfma(u64 a, u64 b, u64 c) {
    u64 r; asm("fma.rn.f32x2 %0, %1, %2, %3;" : "=l"(r) : "l"(a), "l"(b), "l"(c)); return r;
}
__device__ __forceinline__ u64 shfl64(u64 v, int m) {
    float x, y; upk2(v, x, y);
    x = __shfl_xor_sync(0xffffffffu, x, m);
    y = __shfl_xor_sync(0xffffffffu, y, m);
    return pk2(x, y);
}

#define SIGNMASK 0x8000000080000000ULL

// ---------------- prep kernels ----------------
__global__ void prep_var_kernel(const float* __restrict__ theta) {
    int idx = blockIdx.x * blockDim.x + threadIdx.x;        // l*NQ + q
    if (idx >= LAYERS * NQ) return;
    int q = idx % NQ;
    const float* th = theta + idx * 3;
    M2 M = mmul(rz_m(th[2]), mmul(ry_m(th[1]), rx_m(th[0])));
    float c = sqrtf(fmaf(M.m00.x, M.m00.x, M.m00.y * M.m00.y));
    float s = sqrtf(fmaf(M.m10.x, M.m10.x, M.m10.y * M.m10.y));
    float p00 = atan2f(M.m00.y, M.m00.x);
    float p10 = atan2f(M.m10.y, M.m10.x);
    g_alpha[idx] = p10 - p00;
    g_gamma[idx] = -p10 - p00;
    g_cs[idx] = c;
    float t = s / c;
    g_vry[idx] = (q == 11) ? pk2(-t, t) : pk2(t, t);
}

// boundary diagonal l, LAYOUT-B slot indexing (unchanged from R12).
__global__ void prep_diag_kernel() {
    int idx = blockIdx.x * blockDim.x + threadIdx.x;
    if (idx == 0) {
        float C2 = 1.f;
        for (int i = 0; i < LAYERS * NQ; i++) { float cc = g_cs[i]; C2 *= cc * cc; }
        g_scale = C2;
    }
    if (idx >= 3 * 2048) return;
    int l    = idx >> 11;
    int slot = idx & 2047;
    int j    = (slot >> 8) & 7;
    int w    = (slot >> 5) & 7;
    int lane = slot & 31;
    int xp   = (j << 8) | (lane << 3) | w;      // layout B
    const float* al = g_alpha + l * NQ;
    const float* gm = g_gamma + (l + 1) * NQ;
    float rr[2], ii[2];
    #pragma unroll
    for (int h = 0; h < 2; h++) {
        int x  = (xp << 1) | h;
        int ye = x ^ ((x >> 1) & 0x555);
        int yo = x ^ ((x >> 1) & 0x2AA);
        float ang = 0.f;
        for (int q = 0; q < NQ; q++) {
            int p = 11 - q;
            ang += ((ye >> p) & 1) ? 0.5f * al[q] : -0.5f * al[q];
            ang += ((yo >> p) & 1) ? 0.5f * gm[q] : -0.5f * gm[q];
        }
        float sn, cs; sincosf(ang, &sn, &cs);
        rr[h] = cs; ii[h] = sn;
    }
    g_diag[idx] = make_ulonglong2(pk2(rr[0], rr[1]), pk2(ii[0], ii[1]));
}

__global__ void prep_enc_kernel(const float* __restrict__ features, int B) {
    int idx = blockIdx.x * blockDim.x + threadIdx.x;        // e*B*NQ + b*NQ + q
    if (idx >= NENC * B * NQ) return;
    int q = idx % NQ;
    int b = (idx / NQ) % B;
    int e = idx / (B * NQ);
    float f = features[b * NQ + q];
    M2 R = (e & 1) ? ry_m(f) : rx_m(f);
    if (e >= 2) {
        const float r = 0.7071067811865476f;
        M2 H; H.m00 = {r, 0.f}; H.m01 = {r, 0.f}; H.m10 = {r, 0.f}; H.m11 = {-r, 0.f};
        R = mmul(R, H);
    }
    float g = g_gamma[q];          // fold layer-1 gamma diagonal
    float sg, cg; sincosf(0.5f * g, &sg, &cg);
    float2 c0 = cmul(make_float2(R.m00.x, R.m00.y), make_float2(cg, -sg));
    float2 c1 = cmul(make_float2(R.m10.x, R.m10.y), make_float2(cg, sg));
    g_em[idx] = make_float4(c0.x, c0.y, c1.x, c1.y);
}

// ---------------- t-form gate primitives ----------------
// Layout A: amp = (w<<9)|(lane<<4)|(j<<1)|h.
// Layout B: amp = (j<<9)|(lane<<4)|(w<<1)|h  (after transpose3).
// Unit-diagonal Givens G = [[1,-t],[t,1]]; the c factor of every gate is
// folded into g_scale (applied once in reduce_kernel).

// register gate: o0 = A - t*B, o1 = t*A + B. PREJ: input-pair swap (col swap
// from absorbed pre-CNOT); POSTJ: output-pair swap (row swap, post-CNOT).
template<int JB, int PREJ, int POSTJ>
__device__ __forceinline__ void gate_jt(u64 sr[8], u64 si[8], u64 tp) {
    u64 tn = tp ^ SIGNMASK;
    #pragma unroll
    for (int j = 0; j < 8; j++) {
        if (!(j & JB)) {
            const int j1 = j | JB;
            const bool pre  = (PREJ != 0) && ((j & PREJ) != 0);
            const bool post = (POSTJ != 0) && ((j & POSTJ) != 0);
            const int ja = pre ? j1 : j, jb = pre ? j : j1;
            u64 Ar = sr[ja], Ai = si[ja], Br = sr[jb], Bi = si[jb];
            u64 o0r = pfma(tn, Br, Ar), o0i = pfma(tn, Bi, Ai);
            u64 o1r = pfma(tp, Ar, Br), o1i = pfma(tp, Ai, Bi);
            sr[post ? j1 : j] = o0r; si[post ? j1 : j] = o0i;
            sr[post ? j : j1] = o1r; si[post ? j : j1] = o1i;
        }
    }
}

// register gate with RUNTIME column swap (b3's pre-CNOT, ctrl = lane bit 0):
// col swap == swap input operands, then normal t-form.
template<int JB>
__device__ __forceinline__ void gate_jt_cs(u64 sr[8], u64 si[8], u64 tp, bool cs) {
    u64 tn = tp ^ SIGNMASK;
    #pragma unroll
    for (int j = 0; j < 8; j++) {
        if (!(j & JB)) {
            const int j1 = j | JB;
            u64 Ar = cs ? sr[j1] : sr[j], Br = cs ? sr[j] : sr[j1];
            u64 Ai = cs ? si[j1] : si[j], Bi = cs ? si[j] : si[j1];
            sr[j]  = pfma(tn, Br, Ar); si[j]  = pfma(tn, Bi, Ai);
            sr[j1] = pfma(tp, Ar, Br); si[j1] = pfma(tp, Ai, Bi);
        }
    }
}

// lane gate, t-form. row = hi^rxor, scol = hi^cswap, sgnT = row? +t : -t.
// row==scol: out = self + sgnT*other; else: out = sgnT*self + other.
__device__ __forceinline__ void gate_lanert(u64 sr[8], u64 si[8], u64 tp,
                                            int mask, int lane, bool cswap, bool rxor) {
    u64 tn = tp ^ SIGNMASK;
    const bool hi   = (lane & mask) != 0;
    const bool row  = hi ^ rxor;
    const bool eq   = (row == (hi ^ cswap));
    u64 sgnT = row ? tp : tn;
    #pragma unroll
    for (int j = 0; j < 8; j++) {
        u64 orr = shfl64(sr[j], mask);
        u64 oii = shfl64(si[j], mask);
        u64 Xr = eq ? sr[j] : orr, Yr = eq ? orr : sr[j];
        u64 Xi = eq ? si[j] : oii, Yi = eq ? oii : si[j];
        sr[j] = pfma(sgnT, Yr, Xr);
        si[j] = pfma(sgnT, Yi, Xi);
    }
}

// b8 lane gate in LAYOUT B (mask 16), post CNOT row-swap ctrl b9 = j bit 0.
// even j (no swap, eq): out = self + (hi? t:-t)*other
// odd j (row swap, !eq): out = (hi? -t:t)*self + other
__device__ __forceinline__ void gate_lanert_b8(u64 sr[8], u64 si[8], u64 tp, int lane) {
    u64 tn = tp ^ SIGNMASK;
    const bool hi = (lane & 16) != 0;
    u64 sgnE = hi ? tp : tn;
    u64 sgnO = hi ? tn : tp;
    #pragma unroll
    for (int j = 0; j < 8; j++) {
        u64 orr = shfl64(sr[j], 16);
        u64 oii = shfl64(si[j], 16);
        if (j & 1) {
            sr[j] = pfma(sgnO, sr[j], orr);
            si[j] = pfma(sgnO, si[j], oii);
        } else {
            sr[j] = pfma(sgnE, orr, sr[j]);
            si[j] = pfma(sgnE, oii, si[j]);
        }
    }
}

// wire-11 gate on amp bit 0 (within-u64), t-form; post CNOT(ctrl=b1) fused:
// even j: out = a + (-t,+t).swap(a);  odd j (row-swapped): out = swap(a) + (t,-t).a
__device__ __forceinline__ void gate_hr_t(u64 sr[8], u64 si[8], u64 tvA) {
    u64 tvB = tvA ^ SIGNMASK;
    #pragma unroll
    for (int j = 0; j < 8; j++) {
        if (j & 1) {
            u64 nr = pfma(tvB, sr[j], pswap(sr[j]));
            u64 ni = pfma(tvB, si[j], pswap(si[j]));
            sr[j] = nr; si[j] = ni;
        } else {
            sr[j] = pfma(tvA, pswap(sr[j]), sr[j]);
            si[j] = pfma(tvA, pswap(si[j]), si[j]);
        }
    }
}

// boundary diagonal: per-amp complex multiply (state in LAYOUT B)
__device__ __forceinline__ void apply_diag(u64 sr[8], u64 si[8],
                                           const ulonglong2* __restrict__ tab, int tid) {
    #pragma unroll
    for (int j = 0; j < 8; j++) {
        ulonglong2 v = tab[(j << 8) | tid];
        u64 dr = v.x, di = v.y, dni = di ^ SIGNMASK;
        u64 nr = pfma(dni, si[j], pmul(dr, sr[j]));
        u64 ni = pfma(dr,  si[j], pmul(di, sr[j]));
        sr[j] = nr; si[j] = ni;
    }
}

// ---------------- layout transpose: amp bits 1-3 <-> 9-11 ----------------
template<bool HIGHSTORE>
__device__ __forceinline__ void transpose3(u64 sr[8], u64 si[8],
                                           ulonglong2* __restrict__ buf,
                                           int lane, int w) {
    #pragma unroll
    for (int j = 0; j < 8; j++) {
        int u = HIGHSTORE ? ((j << 8) | (lane << 3) | w)
                          : ((w << 8) | (lane << 3) | j);
        buf[u ^ (lane & 7)] = make_ulonglong2(sr[j], si[j]);
    }
    __syncthreads();
    #pragma unroll
    for (int j = 0; j < 8; j++) {
        int u = HIGHSTORE ? ((w << 8) | (lane << 3) | j)
                          : ((j << 8) | (lane << 3) | w);
        ulonglong2 v = buf[u ^ (lane & 7)];
        sr[j] = v.x; si[j] = v.y;
    }
}

// Sweep: identical structure/order to the validated R12 kernel; only the
// gate math is t-form. m = c_vry + l*NQ (1 u64 per wire).
template<bool PRE, bool LAST>
__device__ __forceinline__ void vsweep2(const u64* __restrict__ m,
                                        const ulonglong2* __restrict__ dtab,
                                        u64 sr[8], u64 si[8],
                                        ulonglong2* bufAB, ulonglong2* bufBA,
                                        int lane, int w, int tid) {
    // ---- phase A ----
    if (PRE) gate_jt<1, 2, 0>(sr, si, m[10]);                 // b1 (wire 10), pre c=b2
    else     gate_jt<1, 0, 0>(sr, si, m[10]);
    gate_jt_cs<4>(sr, si, m[8], PRE && (lane & 1));           // b3 (wire 8), pre c=b4
    gate_lanert(sr, si, m[4], 8, lane, PRE && (lane & 16), false);  // b7, pre c=b8
    gate_lanert(sr, si, m[6], 2, lane, PRE && (lane & 4), false);   // b5, pre c=b6
    gate_jt<2, 0, 4>(sr, si, m[9]);                           // b2 (wire 9), post c=b3
    gate_hr_t(sr, si, m[11]);                                 // b0 (wire 11), post c=b1
    gate_lanert(sr, si, m[5], 4, lane, false, (lane & 8) != 0);     // b6, post c=b7
    gate_lanert(sr, si, m[7], 1, lane, false, (lane & 2) != 0);     // b4, post c=b5
    // ---- T(A->B) ----
    transpose3<false>(sr, si, bufAB, lane, w);
    // ---- phase B ----
    gate_jt<4, 0, 0>(sr, si, m[0]);                           // b11 (wire 0)
    if (PRE) gate_jt<1, 2, 0>(sr, si, m[2]);                  // b9 (wire 2), pre c=b10
    else     gate_jt<1, 0, 0>(sr, si, m[2]);
    gate_jt<2, 0, 4>(sr, si, m[1]);                           // b10 (wire 1), post c=b11
    gate_lanert_b8(sr, si, m[3], lane);                       // b8 (wire 3), post c=b9
    if (!LAST) {
        apply_diag(sr, si, dtab, tid);
        transpose3<true>(sr, si, bufBA, lane, w);
    }
}

// ---------------- main kernel ----------------
__global__ __launch_bounds__(NT, 2)
void vqc_reg_kernel(int B)
{
    extern __shared__ ulonglong2 dynbuf[];   // [0..2047] bufAB, [2048..4095] bufBA
    __shared__ float red[NWARP * NQ];
    ulonglong2* bufAB = dynbuf;
    ulonglong2* bufBA = dynbuf + 2048;

    const int b    = blockIdx.x;
    const int e    = blockIdx.y;
    const int tid  = threadIdx.x;
    const int lane = tid & 31;
    const int w    = tid >> 5;

    // ---- encoding: direct product-state construction (layout A) ----
    const float4* col = g_em + (e * B + b) * NQ;
    float2 ph;
    {
        float4 c0 = col[0];
        ph = ((tid >> 7) & 1) ? make_float2(c0.z, c0.w) : make_float2(c0.x, c0.y);
        #pragma unroll
        for (int q = 1; q < 8; q++) {
            float4 cq = col[q];
            float2 v = ((tid >> (7 - q)) & 1) ? make_float2(cq.z, cq.w)
                                              : make_float2(cq.x, cq.y);
            ph = cmul(ph, v);
        }
    }
    u64 sr[8], si[8];
    {
        float4 c8 = col[8], c9 = col[9], c10 = col[10], c11 = col[11];
        float2 t2[2], t4[4], t8[8];
        t2[0] = cmul(ph, make_float2(c8.x, c8.y));
        t2[1] = cmul(ph, make_float2(c8.z, c8.w));
        #pragma unroll
        for (int i = 0; i < 2; i++) {
            t4[i*2+0] = cmul(t2[i], make_float2(c9.x, c9.y));
            t4[i*2+1] = cmul(t2[i], make_float2(c9.z, c9.w));
        }
        #pragma unroll
        for (int i = 0; i < 4; i++) {
            t8[i*2+0] = cmul(t4[i], make_float2(c10.x, c10.y));
            t8[i*2+1] = cmul(t4[i], make_float2(c10.z, c10.w));
        }
        #pragma unroll
        for (int j = 0; j < 8; j++) {
            float2 a  = cmul(t8[j], make_float2(c11.x, c11.y));   // h = 0
            float2 bm = cmul(t8[j], make_float2(c11.z, c11.w));   // h = 1
            sr[j] = pk2(a.x, bm.x);
            si[j] = pk2(a.y, bm.y);
        }
    }

    // ---- variational layers (t-form; c's folded into g_scale) ----
    vsweep2<false, false>(c_vry + 0*NQ, g_diag + 0*2048, sr, si, bufAB, bufBA, lane, w, tid);
    vsweep2<true,  false>(c_vry + 1*NQ, g_diag + 1*2048, sr, si, bufAB, bufBA, lane, w, tid);
    vsweep2<true,  false>(c_vry + 2*NQ, g_diag + 2*2048, sr, si, bufAB, bufBA, lane, w, tid);
    vsweep2<true,  true >(c_vry + 3*NQ, (const ulonglong2*)0, sr, si, bufAB, bufBA, lane, w, tid);
    // state ends in LAYOUT B: amp = (j<<9)|(lane<<4)|(w<<1)|h
    // alpha_4 drops at measurement; layer-4 odd ladder -> epilogue sign
    // permutation: b9^=b10, b7^=b8, b5^=b6, b3^=b4, b1^=b2

    // ---- <Z_q>, layout-B bit mapping ----
    float t[16], tot = 0.f;
    #pragma unroll
    for (int j = 0; j < 8; j++) {
        u64 p2 = pfma(si[j], si[j], pmul(sr[j], sr[j]));
        float p0, p1; upk2(p2, p0, p1);
        t[2*j] = p0; t[2*j+1] = p1;
        tot += p0 + p1;
    }
    float aq0 = 0.f, aq1 = 0.f, aq2 = 0.f, aq11 = 0.f;
    #pragma unroll
    for (int k = 0; k < 16; k++) {
        aq0  += (k & 8) ? -t[k] : t[k];                      // b11   (k bit 3)
        aq1  += (k & 4) ? -t[k] : t[k];                      // b10   (k bit 2)
        aq2  += (((k >> 1) ^ (k >> 2)) & 1) ? -t[k] : t[k];  // b9^b10
        aq11 += (k & 1) ? -t[k] : t[k];                      // b0    (k bit 0)
    }
    float ez[NQ];
    ez[0]  = aq0;
    ez[1]  = aq1;
    ez[2]  = aq2;
    ez[3]  = ((tid >> 4) & 1)                   ? -tot : tot;  // b8
    ez[4]  = (((tid >> 3) ^ (tid >> 4)) & 1)    ? -tot : tot;  // b7^b8
    ez[5]  = ((tid >> 2) & 1)                   ? -tot : tot;  // b6
    ez[6]  = (((tid >> 1) ^ (tid >> 2)) & 1)    ? -tot : tot;  // b5^b6
    ez[7]  = (tid & 1)                          ? -tot : tot;  // b4
    ez[8]  = (((tid >> 7) ^ tid) & 1)           ? -tot : tot;  // b3^b4
    ez[9]  = ((tid >> 6) & 1)                   ? -tot : tot;  // b2
    ez[10] = (((tid >> 5) ^ (tid >> 6)) & 1)    ? -tot : tot;  // b1^b2
    ez[11] = aq11;

    #pragma unroll
    for (int q = 0; q < NQ; q++)
        #pragma unroll
        for (int o = 16; o > 0; o >>= 1)
            ez[q] += __shfl_xor_sync(0xffffffffu, ez[q], o);

    if (lane == 0) {
        #pragma unroll
        for (int q = 0; q < NQ; q++) red[w * NQ + q] = ez[q];
    }
    __syncthreads();
    if (tid < NQ) {
        float acc = 0.f;
        #pragma unroll
        for (int j = 0; j < NWARP; j++) acc += red[j * NQ + tid];
        g_branch[(e * B + b) * NQ + tid] = acc;
    }
}

// ---------------- softmax(alpha)-weighted branch mix + global scale --------
__global__ void reduce_kernel(const float* __restrict__ alpha,
                              float* __restrict__ out, int B)
{
    int idx = blockIdx.x * blockDim.x + threadIdx.x;
    if (idx >= B * NQ) return;
    float a0 = alpha[0], a1 = alpha[1], a2 = alpha[2], a3 = alpha[3];
    float m  = fmaxf(fmaxf(a0, a1), fmaxf(a2, a3));
    float w0 = expf(a0 - m), w1 = expf(a1 - m), w2 = expf(a2 - m), w3 = expf(a3 - m);
    float inv = g_scale / (w0 + w1 + w2 + w3);
    int stride = B * NQ;
    float y = w0 * g_branch[idx]
            + w1 * g_branch[stride + idx]
            + w2 * g_branch[2 * stride + idx]
            + w3 * g_branch[3 * stride + idx];
    out[idx] = y * inv;
}

extern "C" void kernel_launch(void* const* d_in, const int* in_sizes, int n_in,
                              void* d_out, int out_size)
{
    const float* features = (const float*)d_in[0];   // (B, 12)
    const float* theta    = (const float*)d_in[1];   // (4, 12, 3)
    const float* alpha    = (const float*)d_in[2];   // (4,)
    float* out = (float*)d_out;                      // (B, 12)

    int B = in_sizes[0] / NQ;
    if (B > MAXB) B = MAXB;

    const int SMEM_DYN = 4096 * (int)sizeof(ulonglong2);   // 64 KB double buffer
    cudaFuncSetAttribute(vqc_reg_kernel,
                         cudaFuncAttributeMaxDynamicSharedMemorySize, SMEM_DYN);

    prep_var_kernel<<<1, 64>>>(theta);            // writes g_vry, g_cs, g_alpha, g_gamma

    // mirror t-coefficients into __constant__ (D2D async copy, graph-legal)
    void* vry_dev = 0;
    cudaGetSymbolAddress(&vry_dev, g_vry);
    cudaMemcpyToSymbolAsync(c_vry, vry_dev, sizeof(u64) * LAYERS * NQ, 0,
                            cudaMemcpyDeviceToDevice, 0);

    prep_diag_kernel<<<24, 256>>>();              // reads g_alpha/g_gamma/g_cs
    int nenc = NENC * B * NQ;
    prep_enc_kernel<<<(nenc + 255) / 256, 256>>>(features, B);  // reads g_gamma

    dim3 grid(B, NENC);
    vqc_reg_kernel<<<grid, NT, SMEM_DYN>>>(B);

    int n = B * NQ;
    reduce_kernel<<<(n + 255) / 256, 256>>>(alpha, out, B);
}

// round 16
// speedup vs baseline: 1.1680x; 1.1557x over previous
#include <cuda_runtime.h>

#define NQ      12
#define NT      256
#define NWARP   8
#define LAYERS  4
#define NENC    4
#define MAXB    1024

typedef unsigned long long u64;

// ---------------- static device scratch (no allocations) ----------------
__device__ float g_branch[NENC * MAXB * NQ];
// t-form gate coefficients: 1 u64 per (l,q): (t,t); q=11 stores (-t,+t).
__device__ u64   g_vry[LAYERS * NQ];
__constant__ u64 c_vry[LAYERS * NQ];
__device__ float g_cs[LAYERS * NQ];       // per-gate c (for the global scale)
__device__ float g_scale;                 // prod over all 48 gates of c^2
// ZYZ diagonal angles per (l,q)
__device__ float g_alpha[LAYERS * NQ];
__device__ float g_gamma[LAYERS * NQ];
// boundary diagonals: delta0, delta2 in LAYOUT B; delta1 in LAYOUT A.
// slot = (j<<8)|(w<<5)|lane; xp = (j<<8)|(lane<<3)|w (B) or (w<<8)|(lane<<3)|j (A)
__device__ ulonglong2 g_diag[3 * 2048];
// encoding columns (gamma_1 folded): (c0.x, c0.y, c1.x, c1.y)
__device__ float4 g_em[NENC * MAXB * NQ];

// ---------------- scalar complex helpers (prep + encoding) ----------------
__device__ __forceinline__ float2 cmul(float2 a, float2 b) {
    return make_float2(fmaf(a.x, b.x, -a.y * b.y), fmaf(a.x, b.y, a.y * b.x));
}
__device__ __forceinline__ float2 cadd(float2 a, float2 b) {
    return make_float2(a.x + b.x, a.y + b.y);
}
struct M2 { float2 m00, m01, m10, m11; };
__device__ __forceinline__ M2 mmul(const M2& A, const M2& B) {
    M2 C;
    C.m00 = cadd(cmul(A.m00, B.m00), cmul(A.m01, B.m10));
    C.m01 = cadd(cmul(A.m00, B.m01), cmul(A.m01, B.m11));
    C.m10 = cadd(cmul(A.m10, B.m00), cmul(A.m11, B.m10));
    C.m11 = cadd(cmul(A.m10, B.m01), cmul(A.m11, B.m11));
    return C;
}
__device__ __forceinline__ M2 rx_m(float t) {
    float s, c; sincosf(0.5f * t, &s, &c);
    M2 M; M.m00 = {c, 0.f}; M.m01 = {0.f, -s}; M.m10 = {0.f, -s}; M.m11 = {c, 0.f};
    return M;
}
__device__ __forceinline__ M2 ry_m(float t) {
    float s, c; sincosf(0.5f * t, &s, &c);
    M2 M; M.m00 = {c, 0.f}; M.m01 = {-s, 0.f}; M.m10 = {s, 0.f}; M.m11 = {c, 0.f};
    return M;
}
__device__ __forceinline__ M2 rz_m(float t) {
    float s, c; sincosf(0.5f * t, &s, &c);
    M2 M; M.m00 = {c, -s}; M.m01 = {0.f, 0.f}; M.m10 = {0.f, 0.f}; M.m11 = {c, s};
    return M;
}

// ---------------- packed f32x2 primitives ----------------
__device__ __forceinline__ u64 pk2(float x, float y) {
    u64 r; asm("mov.b64 %0, {%1, %2};" : "=l"(r) : "f"(x), "f"(y)); return r;
}
__device__ __forceinline__ void upk2(u64 v, float& x, float& y) {
    asm("mov.b64 {%0, %1}, %2;" : "=f"(x), "=f"(y) : "l"(v));
}
__device__ __forceinline__ u64 pswap(u64 v) {
    float x, y; upk2(v, x, y); return pk2(y, x);
}
__device__ __forceinline__ u64 pmul(u64 a, u64 b) {
    u64 r; asm("mul.rn.f32x2 %0, %1, %2;" : "=l"(r) : "l"(a), "l"(b)); return r;
}
__device__ __forceinline__ u64 pfma(u64 a, u64 b, u64 c) {
    u64 r; asm("fma.rn.f32x2 %0, %1, %2, %3;" : "=l"(r) : "l"(a), "l"(b), "l"(c)); return r;
}
__device__ __forceinline__ u64 shfl64(u64 v, int m) {
    float x, y; upk2(v, x, y);
    x = __shfl_xor_sync(0xffffffffu, x, m);
    y = __shfl_xor_sync(0xffffffffu, y, m);
    return pk2(x, y);
}

#define SIGNMASK 0x8000000080000000ULL
#define PONE     0x3F8000003F800000ULL   /* (1.0f, 1.0f) */

// ---------------- prep kernels ----------------
__global__ void prep_var_kernel(const float* __restrict__ theta) {
    int idx = blockIdx.x * blockDim.x + threadIdx.x;        // l*NQ + q
    if (idx >= LAYERS * NQ) return;
    int q = idx % NQ;
    const float* th = theta + idx * 3;
    M2 M = mmul(rz_m(th[2]), mmul(ry_m(th[1]), rx_m(th[0])));
    float c = sqrtf(fmaf(M.m00.x, M.m00.x, M.m00.y * M.m00.y));
    float s = sqrtf(fmaf(M.m10.x, M.m10.x, M.m10.y * M.m10.y));
    float p00 = atan2f(M.m00.y, M.m00.x);
    float p10 = atan2f(M.m10.y, M.m10.x);
    g_alpha[idx] = p10 - p00;
    g_gamma[idx] = -p10 - p00;
    g_cs[idx] = c;
    float t = s / c;
    g_vry[idx] = (q == 11) ? pk2(-t, t) : pk2(t, t);
}

// boundary diagonal l: delta_l(x) = d_alpha[l](Ce x) * d_gamma[l+1](Co x)
// l = 0, 2: state in layout B at apply point; l = 1: layout A.
__global__ void prep_diag_kernel() {
    int idx = blockIdx.x * blockDim.x + threadIdx.x;
    if (idx == 0) {
        float C2 = 1.f;
        for (int i = 0; i < LAYERS * NQ; i++) { float cc = g_cs[i]; C2 *= cc * cc; }
        g_scale = C2;
    }
    if (idx >= 3 * 2048) return;
    int l    = idx >> 11;
    int slot = idx & 2047;
    int j    = (slot >> 8) & 7;
    int w    = (slot >> 5) & 7;
    int lane = slot & 31;
    int xp   = (l == 1) ? ((w << 8) | (lane << 3) | j)      // layout A
                        : ((j << 8) | (lane << 3) | w);     // layout B
    const float* al = g_alpha + l * NQ;
    const float* gm = g_gamma + (l + 1) * NQ;
    float rr[2], ii[2];
    #pragma unroll
    for (int h = 0; h < 2; h++) {
        int x  = (xp << 1) | h;
        int ye = x ^ ((x >> 1) & 0x555);
        int yo = x ^ ((x >> 1) & 0x2AA);
        float ang = 0.f;
        for (int q = 0; q < NQ; q++) {
            int p = 11 - q;
            ang += ((ye >> p) & 1) ? 0.5f * al[q] : -0.5f * al[q];
            ang += ((yo >> p) & 1) ? 0.5f * gm[q] : -0.5f * gm[q];
        }
        float sn, cs; sincosf(ang, &sn, &cs);
        rr[h] = cs; ii[h] = sn;
    }
    g_diag[idx] = make_ulonglong2(pk2(rr[0], rr[1]), pk2(ii[0], ii[1]));
}

__global__ void prep_enc_kernel(const float* __restrict__ features, int B) {
    int idx = blockIdx.x * blockDim.x + threadIdx.x;        // e*B*NQ + b*NQ + q
    if (idx >= NENC * B * NQ) return;
    int q = idx % NQ;
    int b = (idx / NQ) % B;
    int e = idx / (B * NQ);
    float f = features[b * NQ + q];
    M2 R = (e & 1) ? ry_m(f) : rx_m(f);
    if (e >= 2) {
        const float r = 0.7071067811865476f;
        M2 H; H.m00 = {r, 0.f}; H.m01 = {r, 0.f}; H.m10 = {r, 0.f}; H.m11 = {-r, 0.f};
        R = mmul(R, H);
    }
    float g = g_gamma[q];          // fold layer-1 gamma diagonal
    float sg, cg; sincosf(0.5f * g, &sg, &cg);
    float2 c0 = cmul(make_float2(R.m00.x, R.m00.y), make_float2(cg, -sg));
    float2 c1 = cmul(make_float2(R.m10.x, R.m10.y), make_float2(cg, sg));
    g_em[idx] = make_float4(c0.x, c0.y, c1.x, c1.y);
}

// ---------------- t-form gate primitives ----------------
// Layout A: amp = (w<<9)|(lane<<4)|(j<<1)|h.
// Layout B: amp = (j<<9)|(lane<<4)|(w<<1)|h.

template<int JB, int PREJ, int POSTJ>
__device__ __forceinline__ void gate_jt(u64 sr[8], u64 si[8], u64 tp) {
    u64 tn = tp ^ SIGNMASK;
    #pragma unroll
    for (int j = 0; j < 8; j++) {
        if (!(j & JB)) {
            const int j1 = j | JB;
            const bool pre  = (PREJ != 0) && ((j & PREJ) != 0);
            const bool post = (POSTJ != 0) && ((j & POSTJ) != 0);
            const int ja = pre ? j1 : j, jb = pre ? j : j1;
            u64 Ar = sr[ja], Ai = si[ja], Br = sr[jb], Bi = si[jb];
            u64 o0r = pfma(tn, Br, Ar), o0i = pfma(tn, Bi, Ai);
            u64 o1r = pfma(tp, Ar, Br), o1i = pfma(tp, Ai, Bi);
            sr[post ? j1 : j] = o0r; si[post ? j1 : j] = o0i;
            sr[post ? j : j1] = o1r; si[post ? j : j1] = o1i;
        }
    }
}

// register gate with RUNTIME column swap (b3's pre-CNOT, ctrl = lane bit 0)
template<int JB>
__device__ __forceinline__ void gate_jt_cs(u64 sr[8], u64 si[8], u64 tp, bool cs) {
    u64 tn = tp ^ SIGNMASK;
    #pragma unroll
    for (int j = 0; j < 8; j++) {
        if (!(j & JB)) {
            const int j1 = j | JB;
            u64 Ar = cs ? sr[j1] : sr[j], Br = cs ? sr[j] : sr[j1];
            u64 Ai = cs ? si[j1] : si[j], Bi = cs ? si[j] : si[j1];
            sr[j]  = pfma(tn, Br, Ar); si[j]  = pfma(tn, Bi, Ai);
            sr[j1] = pfma(tp, Ar, Br); si[j1] = pfma(tp, Ai, Bi);
        }
    }
}

// lane gate, SEL-free: out = T1*self + T2*other, (T1,T2) in {(1,sgnT),(sgnT,1)}
__device__ __forceinline__ void gate_lanert(u64 sr[8], u64 si[8], u64 tp,
                                            int mask, int lane, bool cswap, bool rxor) {
    u64 tn = tp ^ SIGNMASK;
    const bool hi  = (lane & mask) != 0;
    const bool row = hi ^ rxor;
    const bool eq  = (row == (hi ^ cswap));
    u64 sgnT = row ? tp : tn;
    u64 T1 = eq ? (u64)PONE : sgnT;
    u64 T2 = eq ? sgnT : (u64)PONE;
    #pragma unroll
    for (int j = 0; j < 8; j++) {
        u64 orr = shfl64(sr[j], mask);
        u64 oii = shfl64(si[j], mask);
        sr[j] = pfma(T2, orr, pmul(T1, sr[j]));
        si[j] = pfma(T2, oii, pmul(T1, si[j]));
    }
}

// b8 lane gate in LAYOUT B (mask 16), post CNOT row-swap ctrl b9 = j bit 0.
__device__ __forceinline__ void gate_lanert_b8(u64 sr[8], u64 si[8], u64 tp, int lane) {
    u64 tn = tp ^ SIGNMASK;
    const bool hi = (lane & 16) != 0;
    u64 sgnE = hi ? tp : tn;
    u64 sgnO = hi ? tn : tp;
    #pragma unroll
    for (int j = 0; j < 8; j++) {
        u64 orr = shfl64(sr[j], 16);
        u64 oii = shfl64(si[j], 16);
        if (j & 1) {
            sr[j] = pfma(sgnO, sr[j], orr);
            si[j] = pfma(sgnO, si[j], oii);
        } else {
            sr[j] = pfma(sgnE, orr, sr[j]);
            si[j] = pfma(sgnE, oii, si[j]);
        }
    }
}

// wire-11 gate on amp bit 0 (within-u64), t-form; post CNOT(ctrl=b1) fused.
__device__ __forceinline__ void gate_hr_t(u64 sr[8], u64 si[8], u64 tvA) {
    u64 tvB = tvA ^ SIGNMASK;
    #pragma unroll
    for (int j = 0; j < 8; j++) {
        if (j & 1) {
            u64 nr = pfma(tvB, sr[j], pswap(sr[j]));
            u64 ni = pfma(tvB, si[j], pswap(si[j]));
            sr[j] = nr; si[j] = ni;
        } else {
            sr[j] = pfma(tvA, pswap(sr[j]), sr[j]);
            si[j] = pfma(tvA, pswap(si[j]), si[j]);
        }
    }
}

// boundary diagonal (table layout matches current state layout)
__device__ __forceinline__ void apply_diag(u64 sr[8], u64 si[8],
                                           const ulonglong2* __restrict__ tab, int tid) {
    #pragma unroll
    for (int j = 0; j < 8; j++) {
        ulonglong2 v = tab[(j << 8) | tid];
        u64 dr = v.x, di = v.y, dni = di ^ SIGNMASK;
        u64 nr = pfma(dni, si[j], pmul(dr, sr[j]));
        u64 ni = pfma(dr,  si[j], pmul(di, sr[j]));
        sr[j] = nr; si[j] = ni;
    }
}

// ---------------- layout transpose: amp bits 1-3 <-> 9-11 ----------------
template<bool HIGHSTORE>
__device__ __forceinline__ void transpose3(u64 sr[8], u64 si[8],
                                           ulonglong2* __restrict__ buf,
                                           int lane, int w) {
    #pragma unroll
    for (int j = 0; j < 8; j++) {
        int u = HIGHSTORE ? ((j << 8) | (lane << 3) | w)
                          : ((w << 8) | (lane << 3) | j);
        buf[u ^ (lane & 7)] = make_ulonglong2(sr[j], si[j]);
    }
    __syncthreads();
    #pragma unroll
    for (int j = 0; j < 8; j++) {
        int u = HIGHSTORE ? ((w << 8) | (lane << 3) | j)
                          : ((j << 8) | (lane << 3) | w);
        ulonglong2 v = buf[u ^ (lane & 7)];
        sr[j] = v.x; si[j] = v.y;
    }
}

// ---------------- phase groups ----------------
// Phase A (layout A), layer m. Gates b0-b7 (+ b8 when B8).
// Order: pres b1,b3,b7,b5 -> b8 (after b7: its fused pre-CNOT(8,7) touches b8)
// -> posts b2,b0,b6,b4.
template<bool PRE, bool B8>
__device__ __forceinline__ void phaseA(const u64* __restrict__ m,
                                       u64 sr[8], u64 si[8], int lane, int w) {
    if (PRE) gate_jt<1, 2, 0>(sr, si, m[10]);                // b1 (w10), pre c=b2
    else     gate_jt<1, 0, 0>(sr, si, m[10]);
    gate_jt_cs<4>(sr, si, m[8], PRE && (lane & 1));          // b3 (w8), pre c=b4
    gate_lanert(sr, si, m[4], 8, lane, PRE && (lane & 16), false);  // b7 (w4), pre c=b8
    gate_lanert(sr, si, m[6], 2, lane, PRE && (lane & 4), false);   // b5 (w6), pre c=b6
    if (B8)                                                  // b8 (w3), post c=b9 (w bit0)
        gate_lanert(sr, si, m[3], 16, lane, false, (w & 1) != 0);
    gate_jt<2, 0, 4>(sr, si, m[9]);                          // b2 (w9), post c=b3
    gate_hr_t(sr, si, m[11]);                                // b0 (w11), post c=b1
    gate_lanert(sr, si, m[5], 4, lane, false, (lane & 8) != 0);     // b6 (w5), post c=b7
    gate_lanert(sr, si, m[7], 1, lane, false, (lane & 2) != 0);     // b4 (w7), post c=b5
}

// Phase B (layout B), layer m. Gates b9-b11 (+ b8 when B8, must come last).
template<bool PRE, bool B8>
__device__ __forceinline__ void phaseB(const u64* __restrict__ m,
                                       u64 sr[8], u64 si[8], int lane) {
    gate_jt<4, 0, 0>(sr, si, m[0]);                          // b11 (w0)
    if (PRE) gate_jt<1, 2, 0>(sr, si, m[2]);                 // b9 (w2), pre c=b10 (j bit1)
    else     gate_jt<1, 0, 0>(sr, si, m[2]);
    gate_jt<2, 0, 4>(sr, si, m[1]);                          // b10 (w1), post c=b11 (j bit2)
    if (B8) gate_lanert_b8(sr, si, m[3], lane);              // b8 (w3), post c=b9 (j bit0)
}

// ---------------- main kernel ----------------
__global__ __launch_bounds__(NT, 2)
void vqc_reg_kernel(int B)
{
    extern __shared__ ulonglong2 dynbuf[];   // [0..2047] bufAB, [2048..4095] bufBA
    __shared__ float red[NWARP * NQ];
    ulonglong2* bufAB = dynbuf;
    ulonglong2* bufBA = dynbuf + 2048;

    const int b    = blockIdx.x;
    const int e    = blockIdx.y;
    const int tid  = threadIdx.x;
    const int lane = tid & 31;
    const int w    = tid >> 5;

    // ---- encoding: direct product-state construction (layout A) ----
    const float4* col = g_em + (e * B + b) * NQ;
    float2 ph;
    {
        float4 c0 = col[0];
        ph = ((tid >> 7) & 1) ? make_float2(c0.z, c0.w) : make_float2(c0.x, c0.y);
        #pragma unroll
        for (int q = 1; q < 8; q++) {
            float4 cq = col[q];
            float2 v = ((tid >> (7 - q)) & 1) ? make_float2(cq.z, cq.w)
                                              : make_float2(cq.x, cq.y);
            ph = cmul(ph, v);
        }
    }
    u64 sr[8], si[8];
    {
        float4 c8 = col[8], c9 = col[9], c10 = col[10], c11 = col[11];
        float2 t2[2], t4[4], t8[8];
        t2[0] = cmul(ph, make_float2(c8.x, c8.y));
        t2[1] = cmul(ph, make_float2(c8.z, c8.w));
        #pragma unroll
        for (int i = 0; i < 2; i++) {
            t4[i*2+0] = cmul(t2[i], make_float2(c9.x, c9.y));
            t4[i*2+1] = cmul(t2[i], make_float2(c9.z, c9.w));
        }
        #pragma unroll
        for (int i = 0; i < 4; i++) {
            t8[i*2+0] = cmul(t4[i], make_float2(c10.x, c10.y));
            t8[i*2+1] = cmul(t4[i], make_float2(c10.z, c10.w));
        }
        #pragma unroll
        for (int j = 0; j < 8; j++) {
            float2 a  = cmul(t8[j], make_float2(c11.x, c11.y));   // h = 0
            float2 bm = cmul(t8[j], make_float2(c11.z, c11.w));   // h = 1
            sr[j] = pk2(a.x, bm.x);
            si[j] = pk2(a.y, bm.y);
        }
    }

    // ---- variational layers: paired phases, 4 transposes ----
    const u64* m1 = c_vry + 0 * NQ;
    const u64* m2 = c_vry + 1 * NQ;
    const u64* m3 = c_vry + 2 * NQ;
    const u64* m4 = c_vry + 3 * NQ;

    phaseA<false, false>(m1, sr, si, lane, w);        // L1: b0-b7
    transpose3<false>(sr, si, bufAB, lane, w);        // A -> B
    phaseB<false, true >(m1, sr, si, lane);           // L1: b8-b11
    apply_diag(sr, si, g_diag + 0 * 2048, tid);       // delta0 (layout B)
    phaseB<true,  false>(m2, sr, si, lane);           // L2: b9-b11 (b8 deferred)
    transpose3<true >(sr, si, bufBA, lane, w);        // B -> A
    phaseA<true,  true >(m2, sr, si, lane, w);        // L2: b0-b8
    apply_diag(sr, si, g_diag + 1 * 2048, tid);       // delta1 (layout A)
    phaseA<true,  false>(m3, sr, si, lane, w);        // L3: b0-b7
    transpose3<false>(sr, si, bufAB, lane, w);        // A -> B
    phaseB<true,  true >(m3, sr, si, lane);           // L3: b8-b11
    apply_diag(sr, si, g_diag + 2 * 2048, tid);       // delta2 (layout B)
    phaseB<true,  false>(m4, sr, si, lane);           // L4: b9-b11 (b8 deferred)
    transpose3<true >(sr, si, bufBA, lane, w);        // B -> A
    phaseA<true,  true >(m4, sr, si, lane, w);        // L4: b0-b8
    // state ends in LAYOUT A. alpha_4 drops at measurement; layer-4 odd
    // ladder -> epilogue sign permutation: b9^=b10, b7^=b8, b5^=b6, b3^=b4, b1^=b2

    // ---- <Z_q>, layout-A bit mapping ----
    // k = 2j+h: k bit0 = b0, bits 1-3 = b1,b2,b3. tid bits 0-4 = b4-b8,
    // tid bits 5-7 = b9,b10,b11.
    float t[16], tot = 0.f;
    #pragma unroll
    for (int j = 0; j < 8; j++) {
        u64 p2 = pfma(si[j], si[j], pmul(sr[j], sr[j]));
        float p0, p1; upk2(p2, p0, p1);
        t[2*j] = p0; t[2*j+1] = p1;
        tot += p0 + p1;
    }
    const int t7 = (tid >> 7) & 1, t6 = (tid >> 6) & 1, t5 = (tid >> 5) & 1,
              t4b = (tid >> 4) & 1, t3 = (tid >> 3) & 1, t2b = (tid >> 2) & 1,
              t1 = (tid >> 1) & 1, t0 = tid & 1;
    float ez[NQ];
    ez[0] = t7        ? -tot : tot;   // wire0  = b11
    ez[1] = t6        ? -tot : tot;   // wire1  = b10
    ez[2] = (t5 ^ t6) ? -tot : tot;   // wire2  = b9 ^ b10
    ez[3] = t4b       ? -tot : tot;   // wire3  = b8
    ez[4] = (t3 ^ t4b)? -tot : tot;   // wire4  = b7 ^ b8
    ez[5] = t2b       ? -tot : tot;   // wire5  = b6
    ez[6] = (t1 ^ t2b)? -tot : tot;   // wire6  = b5 ^ b6
    ez[7] = t0        ? -tot : tot;   // wire7  = b4
    float a8 = 0.f, a9 = 0.f, a10 = 0.f, a11 = 0.f;
    #pragma unroll
    for (int k = 0; k < 16; k++) {
        a8  += (k & 8) ? -t[k] : t[k];                      // b3 (k bit 3)
        a9  += (k & 4) ? -t[k] : t[k];                      // b2 (k bit 2)
        a10 += (((k >> 1) ^ (k >> 2)) & 1) ? -t[k] : t[k];  // b1 ^ b2
        a11 += (k & 1) ? -t[k] : t[k];                      // b0 (k bit 0)
    }
    ez[8]  = t0 ? -a8 : a8;           // wire8 = b3 ^ b4 (b4 = tid bit 0)
    ez[9]  = a9;                      // wire9 = b2
    ez[10] = a10;                     // wire10 = b1 ^ b2
    ez[11] = a11;                     // wire11 = b0

    #pragma unroll
    for (int q = 0; q < NQ; q++)
        #pragma unroll
        for (int o = 16; o > 0; o >>= 1)
            ez[q] += __shfl_xor_sync(0xffffffffu, ez[q], o);

    if (lane == 0) {
        #pragma unroll
        for (int q = 0; q < NQ; q++) red[w * NQ + q] = ez[q];
    }
    __syncthreads();
    if (tid < NQ) {
        float acc = 0.f;
        #pragma unroll
        for (int j = 0; j < NWARP; j++) acc += red[j * NQ + tid];
        g_branch[(e * B + b) * NQ + tid] = acc;
    }
}

// ---------------- softmax(alpha)-weighted branch mix + global scale --------
__global__ void reduce_kernel(const float* __restrict__ alpha,
                              float* __restrict__ out, int B)
{
    int idx = blockIdx.x * blockDim.x + threadIdx.x;
    if (idx >= B * NQ) return;
    float a0 = alpha[0], a1 = alpha[1], a2 = alpha[2], a3 = alpha[3];
    float m  = fmaxf(fmaxf(a0, a1), fmaxf(a2, a3));
    float w0 = expf(a0 - m), w1 = expf(a1 - m), w2 = expf(a2 - m), w3 = expf(a3 - m);
    float inv = g_scale / (w0 + w1 + w2 + w3);
    int stride = B * NQ;
    float y = w0 * g_branch[idx]
            + w1 * g_branch[stride + idx]
            + w2 * g_branch[2 * stride + idx]
            + w3 * g_branch[3 * stride + idx];
    out[idx] = y * inv;
}

extern "C" void kernel_launch(void* const* d_in, const int* in_sizes, int n_in,
                              void* d_out, int out_size)
{
    const float* features = (const float*)d_in[0];   // (B, 12)
    const float* theta    = (const float*)d_in[1];   // (4, 12, 3)
    const float* alpha    = (const float*)d_in[2];   // (4,)
    float* out = (float*)d_out;                      // (B, 12)

    int B = in_sizes[0] / NQ;
    if (B > MAXB) B = MAXB;

    const int SMEM_DYN = 4096 * (int)sizeof(ulonglong2);   // 64 KB double buffer
    cudaFuncSetAttribute(vqc_reg_kernel,
                         cudaFuncAttributeMaxDynamicSharedMemorySize, SMEM_DYN);

    prep_var_kernel<<<1, 64>>>(theta);            // writes g_vry, g_cs, g_alpha, g_gamma

    // mirror t-coefficients into __constant__ (D2D async copy, graph-legal)
    void* vry_dev = 0;
    cudaGetSymbolAddress(&vry_dev, g_vry);
    cudaMemcpyToSymbolAsync(c_vry, vry_dev, sizeof(u64) * LAYERS * NQ, 0,
                            cudaMemcpyDeviceToDevice, 0);

    prep_diag_kernel<<<24, 256>>>();              // reads g_alpha/g_gamma/g_cs
    int nenc = NENC * B * NQ;
    prep_enc_kernel<<<(nenc + 255) / 256, 256>>>(features, B);  // reads g_gamma

    dim3 grid(B, NENC);
    vqc_reg_kernel<<<grid, NT, SMEM_DYN>>>(B);

    int n = B * NQ;
    reduce_kernel<<<(n + 255) / 256, 256>>>(alpha, out, B);
}